// round 9
// baseline (speedup 1.0000x reference)
#include <cuda_runtime.h>
#include <cuda_fp16.h>
#include <cuda_bf16.h>
#include <cstdint>

// GeoEncoder v8: v7 + Morton counting-sort of points so each warp samples a
// spatially-coherent span -> corner gathers become L1/L2 hits.

#define RES   512
#define RANK  48
#define PADC  64
#define OUT_C 32
#define NBUCK 32768            // 15-bit Morton key (5 bits/axis)

typedef unsigned long long u64;

__device__ __half g_planes_h[3ull * RES * RES * PADC];  // ~100 MB
__device__ __half g_lines_h[3 * RES * PADC];            // 192 KB
__device__ unsigned g_hist[NBUCK];
__device__ unsigned g_cursor[NBUCK];
__device__ float4 g_sorted[1000192];                     // sorted coords + idx

// ---- packed f32x2 helpers -------------------------------------------------
__device__ __forceinline__ u64 pk2(float lo, float hi) {
    u64 r; asm("mov.b64 %0,{%1,%2};" : "=l"(r) : "f"(lo), "f"(hi)); return r;
}
__device__ __forceinline__ float2 upk2(u64 a) {
    float2 f; asm("mov.b64 {%0,%1},%2;" : "=f"(f.x), "=f"(f.y) : "l"(a)); return f;
}
__device__ __forceinline__ u64 f2fma(u64 a, u64 b, u64 c) {
    u64 d; asm("fma.rn.f32x2 %0,%1,%2,%3;" : "=l"(d) : "l"(a), "l"(b), "l"(c)); return d;
}
__device__ __forceinline__ u64 f2mul(u64 a, u64 b) {
    u64 d; asm("mul.rn.f32x2 %0,%1,%2;" : "=l"(d) : "l"(a), "l"(b)); return d;
}
__device__ __forceinline__ u64 h2f2(unsigned h) {
    float2 f = __half22float2(*reinterpret_cast<const __half2*>(&h));
    return pk2(f.x, f.y);
}
__device__ __forceinline__ u64 mkpair(unsigned lo, unsigned hi) {
    u64 r; asm("mov.b64 %0,{%1,%2};" : "=l"(r) : "r"(lo), "r"(hi)); return r;
}

// ---- Morton helpers -------------------------------------------------------
__device__ __forceinline__ unsigned spread3(unsigned x) {
    x &= 0x3ff;
    x = (x | (x << 16)) & 0x030000FF;
    x = (x | (x <<  8)) & 0x0300F00F;
    x = (x | (x <<  4)) & 0x030C30C3;
    x = (x | (x <<  2)) & 0x09249249;
    return x;
}
__device__ __forceinline__ unsigned morton_key(float x, float y, float z) {
    unsigned xq = min(31, (int)(fminf(fmaxf(x, 0.0f), 0.999999f) * 32.0f));
    unsigned yq = min(31, (int)(fminf(fmaxf(y, 0.0f), 0.999999f) * 32.0f));
    unsigned zq = min(31, (int)(fminf(fmaxf(z, 0.0f), 0.999999f) * 32.0f));
    return spread3(xq) | (spread3(yq) << 1) | (spread3(zq) << 2);
}

// ---------------------------------------------------------------------------
// Prep: planes [R][512][512] f32 -> [p][y][x][64] fp16 (pad 0);
//       lines  [R][512]       -> [l][z][64] fp16 (pad 0).  z==3 does lines.
// ---------------------------------------------------------------------------
__global__ void prep_grids(const float* __restrict__ pxy,
                           const float* __restrict__ pxz,
                           const float* __restrict__ pyz,
                           const float* __restrict__ lz,
                           const float* __restrict__ ly,
                           const float* __restrict__ lx) {
    if (blockIdx.z == 3) {
        const int total = 3 * RES * PADC;
        int i = ((blockIdx.y * gridDim.x + blockIdx.x) * blockDim.x) + threadIdx.x;
        if (i < total) {
            int p   = i / (RES * PADC);
            int rem = i - p * (RES * PADC);
            int z   = rem / PADC;
            int r   = rem - z * PADC;
            const float* in = (p == 0) ? lz : (p == 1) ? ly : lx;
            g_lines_h[i] = (r < RANK) ? __float2half(in[r * RES + z]) : __half(0.0f);
        }
        return;
    }
    __shared__ float s[128 * 49];
    const int p  = blockIdx.z;
    const int y  = blockIdx.y;
    const int xb = blockIdx.x * 128;
    const float* in = (p == 0) ? pxy : (p == 1) ? pxz : pyz;

    for (int i = threadIdx.x; i < RANK * 128; i += blockDim.x) {
        int r  = i >> 7;
        int xl = i & 127;
        s[xl * 49 + r] = in[(size_t)r * (RES * RES) + (size_t)y * RES + xb + xl];
    }
    __syncthreads();

    __half2* outp = reinterpret_cast<__half2*>(
        g_planes_h + ((size_t)p * (RES * RES) + (size_t)y * RES + xb) * PADC);
    for (int i = threadIdx.x; i < 128 * (PADC / 2); i += blockDim.x) {
        int xl = i >> 5;
        int c  = (i & 31) * 2;
        float a = (c     < RANK) ? s[xl * 49 + c]     : 0.0f;
        float b = (c + 1 < RANK) ? s[xl * 49 + c + 1] : 0.0f;
        outp[i] = __floats2half2_rn(a, b);
    }
}

// ---------------------------------------------------------------------------
// Sorting pipeline: zero hist -> histogram -> scan -> scatter
// ---------------------------------------------------------------------------
__global__ void zero_hist() {
    int i = blockIdx.x * blockDim.x + threadIdx.x;
    if (i < NBUCK) g_hist[i] = 0;
}

__global__ void hist_kernel(const float* __restrict__ coords, int npts) {
    int i = blockIdx.x * blockDim.x + threadIdx.x;
    if (i < npts) {
        float x = coords[3 * i], y = coords[3 * i + 1], z = coords[3 * i + 2];
        atomicAdd(&g_hist[morton_key(x, y, z)], 1u);
    }
}

__global__ void __launch_bounds__(1024) scan_hist() {
    __shared__ unsigned partial[1024];
    const int tid  = threadIdx.x;
    const int base = tid * (NBUCK / 1024);
    unsigned local[NBUCK / 1024];
    unsigned sum = 0;
    #pragma unroll
    for (int j = 0; j < NBUCK / 1024; j++) { local[j] = sum; sum += g_hist[base + j]; }
    partial[tid] = sum;
    __syncthreads();
    for (int off = 1; off < 1024; off <<= 1) {
        unsigned v = (tid >= off) ? partial[tid - off] : 0u;
        __syncthreads();
        partial[tid] += v;
        __syncthreads();
    }
    const unsigned excl = partial[tid] - sum;
    #pragma unroll
    for (int j = 0; j < NBUCK / 1024; j++) g_cursor[base + j] = excl + local[j];
}

__global__ void scatter_kernel(const float* __restrict__ coords, int npts) {
    int i = blockIdx.x * blockDim.x + threadIdx.x;
    if (i < npts) {
        float x = coords[3 * i], y = coords[3 * i + 1], z = coords[3 * i + 2];
        unsigned pos = atomicAdd(&g_cursor[morton_key(x, y, z)], 1u);
        g_sorted[pos] = make_float4(x, y, z, __int_as_float(i));
    }
}

// ---------------------------------------------------------------------------
// Main kernel. Warp = 4 sorted points; 8 lanes/point, 8 channels/lane.
// Each warp owns a CONTIGUOUS sorted span -> L1-resident texel neighborhood.
// ---------------------------------------------------------------------------
__global__ void __launch_bounds__(256, 4)
geo_main(const float* __restrict__ projw,
         const float* __restrict__ projb,
         float* __restrict__ out, int npts) {
    __shared__ alignas(16) u64 s_vm[8][4][32];
    __shared__ u64 s_w[24][OUT_C];

    const int tid  = threadIdx.x;
    const int warp = tid >> 5;
    const int lane = tid & 31;
    const int sp   = lane >> 3;
    const int t    = lane & 7;
    const int o    = lane;

    for (int i = tid; i < 24 * OUT_C; i += blockDim.x) {
        int c2 = i >> 5, oo = i & 31;
        s_w[c2][oo] = pk2(projw[oo * RANK + 2 * c2], projw[oo * RANK + 2 * c2 + 1]);
    }
    __syncthreads();
    const float bo = projb[o];

    // Contiguous span per warp (multiple of 4).
    const int warp_global = blockIdx.x * (blockDim.x >> 5) + warp;
    const int warp_count  = gridDim.x * (blockDim.x >> 5);
    const int span = ((npts + warp_count * 4 - 1) / (warp_count * 4)) * 4;
    const int pstart = warp_global * span;
    const int pend   = min(npts, pstart + span);

    for (int pb = pstart; pb < pend; pb += 4) {
        // Lanes 0-3 fetch sorted coord records; everyone shuffles from lane sp.
        float4 cvv = make_float4(0.f, 0.f, 0.f, 0.f);
        if (lane < 4) cvv = g_sorted[min(pb + lane, npts - 1)];
        const float cx = __shfl_sync(0xffffffffu, cvv.x, sp) * 2.0f - 1.0f;
        const float cy = __shfl_sync(0xffffffffu, cvv.y, sp) * 2.0f - 1.0f;
        const float cz = __shfl_sync(0xffffffffu, cvv.z, sp) * 2.0f - 1.0f;

        u64 acc[4];
        #pragma unroll
        for (int k = 0; k < 4; k++) acc[k] = pk2(0.0f, 0.0f);

        #pragma unroll
        for (int q = 0; q < 3; q++) {
            const float gx = (q == 2) ? cy : cx;
            const float gy = (q == 0) ? cy : cz;
            const float gl = (q == 0) ? cz : ((q == 1) ? cy : cx);

            float px = fminf(fmaxf((gx + 1.0f) * 0.5f * 511.0f, 0.0f), 511.0f);
            float py = fminf(fmaxf((gy + 1.0f) * 0.5f * 511.0f, 0.0f), 511.0f);
            float pz = fminf(fmaxf((gl + 1.0f) * 0.5f * 511.0f, 0.0f), 511.0f);
            const int x0 = (int)floorf(px), y0 = (int)floorf(py), z0 = (int)floorf(pz);
            const int x1 = min(x0 + 1, 511), y1 = min(y0 + 1, 511), z1 = min(z0 + 1, 511);
            const float wx = px - (float)x0;
            const float wy = py - (float)y0;
            const float wz = pz - (float)z0;

            const float w00 = (1.0f - wy) * (1.0f - wx);
            const float w01 = (1.0f - wy) * wx;
            const float w10 = wy * (1.0f - wx);
            const float w11 = wy * wx;
            const u64 w00p = pk2(w00, w00), w01p = pk2(w01, w01);
            const u64 w10p = pk2(w10, w10), w11p = pk2(w11, w11);
            const u64 lz0p = pk2(1.0f - wz, 1.0f - wz), wzp = pk2(wz, wz);

            const __half* gp = g_planes_h + (size_t)q * (RES * RES * PADC);
            const uint4 u00 = __ldg(reinterpret_cast<const uint4*>(gp + ((size_t)(y0 * RES) + x0) * PADC) + t);
            const uint4 u01 = __ldg(reinterpret_cast<const uint4*>(gp + ((size_t)(y0 * RES) + x1) * PADC) + t);
            const uint4 u10 = __ldg(reinterpret_cast<const uint4*>(gp + ((size_t)(y1 * RES) + x0) * PADC) + t);
            const uint4 u11 = __ldg(reinterpret_cast<const uint4*>(gp + ((size_t)(y1 * RES) + x1) * PADC) + t);
            const uint4 a0  = __ldg(reinterpret_cast<const uint4*>(g_lines_h + (q * RES + z0) * PADC) + t);
            const uint4 a1  = __ldg(reinterpret_cast<const uint4*>(g_lines_h + (q * RES + z1) * PADC) + t);

            #pragma unroll
            for (int k = 0; k < 4; k++) {
                const u64 f00 = h2f2((&u00.x)[k]);
                const u64 f01 = h2f2((&u01.x)[k]);
                const u64 f10 = h2f2((&u10.x)[k]);
                const u64 f11 = h2f2((&u11.x)[k]);
                const u64 g0  = h2f2((&a0.x)[k]);
                const u64 g1  = h2f2((&a1.x)[k]);

                const u64 pv = f2fma(f00, w00p,
                                f2fma(f01, w01p,
                                 f2fma(f10, w10p, f2mul(f11, w11p))));
                const u64 lv = f2fma(g0, lz0p, f2mul(g1, wzp));
                acc[k] = f2fma(pv, lv, acc[k]);
            }
        }

        // Stage vm (t=6,7 write zero pad in-bounds).
        {
            const float2 a0 = upk2(acc[0]), a1 = upk2(acc[1]);
            const float2 a2 = upk2(acc[2]), a3 = upk2(acc[3]);
            float4* dst = reinterpret_cast<float4*>(&s_vm[warp][sp][t * 4]);
            dst[0] = make_float4(a0.x, a0.y, a1.x, a1.y);
            dst[1] = make_float4(a2.x, a2.y, a3.x, a3.y);
        }
        __syncwarp();

        // Matvec, c4-outer; scatter by original index (one 128B line/point).
        {
            u64 s2[4];
            #pragma unroll
            for (int h = 0; h < 4; h++) s2[h] = pk2(0.0f, 0.0f);

            #pragma unroll
            for (int c4 = 0; c4 < 12; c4++) {
                const u64 w0 = s_w[2 * c4 + 0][o];
                const u64 w1 = s_w[2 * c4 + 1][o];
                #pragma unroll
                for (int h = 0; h < 4; h++) {
                    const uint4 v = reinterpret_cast<const uint4*>(s_vm[warp][h])[c4];
                    s2[h] = f2fma(mkpair(v.x, v.y), w0, s2[h]);
                    s2[h] = f2fma(mkpair(v.z, v.w), w1, s2[h]);
                }
            }

            #pragma unroll
            for (int h = 0; h < 4; h++) {
                const int idx = __float_as_int(__shfl_sync(0xffffffffu, cvv.w, h));
                if (pb + h < npts) {
                    const float2 f = upk2(s2[h]);
                    __stcs(out + (size_t)idx * OUT_C + o, f.x + f.y + bo);
                }
            }
        }
        __syncwarp();
    }
}

// ---------------------------------------------------------------------------
extern "C" void kernel_launch(void* const* d_in, const int* in_sizes, int n_in,
                              void* d_out, int out_size) {
    const float* coords = (const float*)d_in[0];
    const float* pxy    = (const float*)d_in[1];
    const float* pxz    = (const float*)d_in[2];
    const float* pyz    = (const float*)d_in[3];
    const float* lz     = (const float*)d_in[4];
    const float* ly     = (const float*)d_in[5];
    const float* lx     = (const float*)d_in[6];
    const float* pw     = (const float*)d_in[7];
    const float* pbias  = (const float*)d_in[8];
    float* outp = (float*)d_out;
    const int npts = in_sizes[0] / 3;

    dim3 tgrid(4, RES, 4);
    prep_grids<<<tgrid, 256>>>(pxy, pxz, pyz, lz, ly, lx);
    zero_hist<<<(NBUCK + 255) / 256, 256>>>();
    hist_kernel<<<(npts + 255) / 256, 256>>>(coords, npts);
    scan_hist<<<1, 1024>>>();
    scatter_kernel<<<(npts + 255) / 256, 256>>>(coords, npts);
    geo_main<<<592, 256>>>(pw, pbias, outp, npts);
}

// round 10
// speedup vs baseline: 1.0339x; 1.0339x over previous
#include <cuda_runtime.h>
#include <cuda_fp16.h>
#include <cuda_bf16.h>
#include <cstdint>

// GeoEncoder v9: Morton sort kept, overhead slashed (parallel 3-phase scan),
// CTA-interleaved spans so all 8 warps of a CTA share one L1 texel window,
// coord prefetch + streaming hints on sort traffic.

#define RES   512
#define RANK  48
#define PADC  64
#define OUT_C 32
#define NBUCK 32768            // 15-bit Morton key (5 bits/axis)

typedef unsigned long long u64;

__device__ __half g_planes_h[3ull * RES * RES * PADC];  // ~100 MB
__device__ __half g_lines_h[3 * RES * PADC];            // 192 KB
__device__ unsigned g_hist[NBUCK];
__device__ unsigned g_cursor[NBUCK];
__device__ unsigned g_blocksum[128];
__device__ unsigned g_blockoff[128];
__device__ float4 g_sorted[1000192];                     // sorted coords + idx

// ---- packed f32x2 helpers -------------------------------------------------
__device__ __forceinline__ u64 pk2(float lo, float hi) {
    u64 r; asm("mov.b64 %0,{%1,%2};" : "=l"(r) : "f"(lo), "f"(hi)); return r;
}
__device__ __forceinline__ float2 upk2(u64 a) {
    float2 f; asm("mov.b64 {%0,%1},%2;" : "=f"(f.x), "=f"(f.y) : "l"(a)); return f;
}
__device__ __forceinline__ u64 f2fma(u64 a, u64 b, u64 c) {
    u64 d; asm("fma.rn.f32x2 %0,%1,%2,%3;" : "=l"(d) : "l"(a), "l"(b), "l"(c)); return d;
}
__device__ __forceinline__ u64 f2mul(u64 a, u64 b) {
    u64 d; asm("mul.rn.f32x2 %0,%1,%2;" : "=l"(d) : "l"(a), "l"(b)); return d;
}
__device__ __forceinline__ u64 h2f2(unsigned h) {
    float2 f = __half22float2(*reinterpret_cast<const __half2*>(&h));
    return pk2(f.x, f.y);
}
__device__ __forceinline__ u64 mkpair(unsigned lo, unsigned hi) {
    u64 r; asm("mov.b64 %0,{%1,%2};" : "=l"(r) : "r"(lo), "r"(hi)); return r;
}

// ---- Morton helpers -------------------------------------------------------
__device__ __forceinline__ unsigned spread3(unsigned x) {
    x &= 0x3ff;
    x = (x | (x << 16)) & 0x030000FF;
    x = (x | (x <<  8)) & 0x0300F00F;
    x = (x | (x <<  4)) & 0x030C30C3;
    x = (x | (x <<  2)) & 0x09249249;
    return x;
}
__device__ __forceinline__ unsigned morton_key(float x, float y, float z) {
    unsigned xq = min(31, (int)(fminf(fmaxf(x, 0.0f), 0.999999f) * 32.0f));
    unsigned yq = min(31, (int)(fminf(fmaxf(y, 0.0f), 0.999999f) * 32.0f));
    unsigned zq = min(31, (int)(fminf(fmaxf(z, 0.0f), 0.999999f) * 32.0f));
    return spread3(xq) | (spread3(yq) << 1) | (spread3(zq) << 2);
}

// ---------------------------------------------------------------------------
// Prep: planes -> [p][y][x][64] fp16; lines -> [l][z][64] fp16. z==3 = lines.
// ---------------------------------------------------------------------------
__global__ void prep_grids(const float* __restrict__ pxy,
                           const float* __restrict__ pxz,
                           const float* __restrict__ pyz,
                           const float* __restrict__ lz,
                           const float* __restrict__ ly,
                           const float* __restrict__ lx) {
    if (blockIdx.z == 3) {
        const int total = 3 * RES * PADC;
        int i = ((blockIdx.y * gridDim.x + blockIdx.x) * blockDim.x) + threadIdx.x;
        if (i < total) {
            int p   = i / (RES * PADC);
            int rem = i - p * (RES * PADC);
            int z   = rem / PADC;
            int r   = rem - z * PADC;
            const float* in = (p == 0) ? lz : (p == 1) ? ly : lx;
            g_lines_h[i] = (r < RANK) ? __float2half(in[r * RES + z]) : __half(0.0f);
        }
        return;
    }
    __shared__ float s[128 * 49];
    const int p  = blockIdx.z;
    const int y  = blockIdx.y;
    const int xb = blockIdx.x * 128;
    const float* in = (p == 0) ? pxy : (p == 1) ? pxz : pyz;

    for (int i = threadIdx.x; i < RANK * 128; i += blockDim.x) {
        int r  = i >> 7;
        int xl = i & 127;
        s[xl * 49 + r] = in[(size_t)r * (RES * RES) + (size_t)y * RES + xb + xl];
    }
    __syncthreads();

    __half2* outp = reinterpret_cast<__half2*>(
        g_planes_h + ((size_t)p * (RES * RES) + (size_t)y * RES + xb) * PADC);
    for (int i = threadIdx.x; i < 128 * (PADC / 2); i += blockDim.x) {
        int xl = i >> 5;
        int c  = (i & 31) * 2;
        float a = (c     < RANK) ? s[xl * 49 + c]     : 0.0f;
        float b = (c + 1 < RANK) ? s[xl * 49 + c + 1] : 0.0f;
        outp[i] = __floats2half2_rn(a, b);
    }
}

// ---------------------------------------------------------------------------
// Sort pipeline: zero -> hist -> (blocksum -> blockscan -> localscan) -> scatter
// ---------------------------------------------------------------------------
__global__ void zero_hist() {
    int i = blockIdx.x * blockDim.x + threadIdx.x;
    if (i < NBUCK) g_hist[i] = 0;
}

__global__ void hist_kernel(const float* __restrict__ coords, int npts) {
    int i = blockIdx.x * blockDim.x + threadIdx.x;
    if (i < npts) {
        float x = __ldcs(coords + 3 * i), y = __ldcs(coords + 3 * i + 1),
              z = __ldcs(coords + 3 * i + 2);
        atomicAdd(&g_hist[morton_key(x, y, z)], 1u);
    }
}

// Phase 1: per-block (256 bins) totals. 128 blocks x 256 threads.
__global__ void scan_blocksum() {
    __shared__ unsigned red[256];
    const int tid = threadIdx.x;
    unsigned v = g_hist[blockIdx.x * 256 + tid];
    red[tid] = v;
    __syncthreads();
    for (int off = 128; off > 0; off >>= 1) {
        if (tid < off) red[tid] += red[tid + off];
        __syncthreads();
    }
    if (tid == 0) g_blocksum[blockIdx.x] = red[0];
}

// Phase 2: exclusive scan of 128 block totals. 1 block x 128 threads.
__global__ void scan_blockoff() {
    __shared__ unsigned s[128];
    const int tid = threadIdx.x;
    unsigned v = g_blocksum[tid];
    s[tid] = v;
    __syncthreads();
    for (int off = 1; off < 128; off <<= 1) {
        unsigned u = (tid >= off) ? s[tid - off] : 0u;
        __syncthreads();
        s[tid] += u;
        __syncthreads();
    }
    g_blockoff[tid] = s[tid] - v;   // exclusive
}

// Phase 3: local exclusive scan of 256 bins + block offset -> g_cursor.
__global__ void scan_local() {
    __shared__ unsigned s[256];
    const int tid  = threadIdx.x;
    const int base = blockIdx.x * 256;
    unsigned v = g_hist[base + tid];
    s[tid] = v;
    __syncthreads();
    for (int off = 1; off < 256; off <<= 1) {
        unsigned u = (tid >= off) ? s[tid - off] : 0u;
        __syncthreads();
        s[tid] += u;
        __syncthreads();
    }
    g_cursor[base + tid] = s[tid] - v + g_blockoff[blockIdx.x];
}

__global__ void scatter_kernel(const float* __restrict__ coords, int npts) {
    int i = blockIdx.x * blockDim.x + threadIdx.x;
    if (i < npts) {
        float x = __ldcs(coords + 3 * i), y = __ldcs(coords + 3 * i + 1),
              z = __ldcs(coords + 3 * i + 2);
        unsigned pos = atomicAdd(&g_cursor[morton_key(x, y, z)], 1u);
        __stcs(&g_sorted[pos], make_float4(x, y, z, __int_as_float(i)));
    }
}

// ---------------------------------------------------------------------------
// Main kernel. CTA owns a contiguous sorted block; its 8 warps process
// INTERLEAVED 4-point groups (32 consecutive points per CTA-iteration) so
// all warps share one L1 texel window. Coord prefetch double-buffers.
// ---------------------------------------------------------------------------
__global__ void __launch_bounds__(256, 4)
geo_main(const float* __restrict__ projw,
         const float* __restrict__ projb,
         float* __restrict__ out, int npts) {
    __shared__ alignas(16) u64 s_vm[8][4][32];
    __shared__ u64 s_w[24][OUT_C];

    const int tid  = threadIdx.x;
    const int warp = tid >> 5;
    const int lane = tid & 31;
    const int sp   = lane >> 3;
    const int t    = lane & 7;
    const int o    = lane;

    for (int i = tid; i < 24 * OUT_C; i += blockDim.x) {
        int c2 = i >> 5, oo = i & 31;
        s_w[c2][oo] = pk2(projw[oo * RANK + 2 * c2], projw[oo * RANK + 2 * c2 + 1]);
    }
    __syncthreads();
    const float bo = projb[o];

    // CTA-contiguous block, warp-interleaved 4-point groups.
    const int perCta = ((npts + gridDim.x * 32 - 1) / (gridDim.x * 32)) * 32;
    const int cbase  = blockIdx.x * perCta;
    const int cend   = min(npts, cbase + perCta);

    int pb = cbase + warp * 4;
    // Prefetch first coords.
    float4 cvv = make_float4(0.f, 0.f, 0.f, 0.f);
    if (pb < cend && lane < 4)
        cvv = __ldcs(&g_sorted[min(pb + lane, npts - 1)]);

    for (; pb < cend; pb += 32) {
        // Prefetch next iteration's coords (independent of current work).
        float4 cvn = make_float4(0.f, 0.f, 0.f, 0.f);
        const int pbn = pb + 32;
        if (pbn < cend && lane < 4)
            cvn = __ldcs(&g_sorted[min(pbn + lane, npts - 1)]);

        const float cx = __shfl_sync(0xffffffffu, cvv.x, sp) * 2.0f - 1.0f;
        const float cy = __shfl_sync(0xffffffffu, cvv.y, sp) * 2.0f - 1.0f;
        const float cz = __shfl_sync(0xffffffffu, cvv.z, sp) * 2.0f - 1.0f;

        u64 acc[4];
        #pragma unroll
        for (int k = 0; k < 4; k++) acc[k] = pk2(0.0f, 0.0f);

        #pragma unroll
        for (int q = 0; q < 3; q++) {
            const float gx = (q == 2) ? cy : cx;
            const float gy = (q == 0) ? cy : cz;
            const float gl = (q == 0) ? cz : ((q == 1) ? cy : cx);

            float px = fminf(fmaxf((gx + 1.0f) * 0.5f * 511.0f, 0.0f), 511.0f);
            float py = fminf(fmaxf((gy + 1.0f) * 0.5f * 511.0f, 0.0f), 511.0f);
            float pz = fminf(fmaxf((gl + 1.0f) * 0.5f * 511.0f, 0.0f), 511.0f);
            const int x0 = (int)floorf(px), y0 = (int)floorf(py), z0 = (int)floorf(pz);
            const int x1 = min(x0 + 1, 511), y1 = min(y0 + 1, 511), z1 = min(z0 + 1, 511);
            const float wx = px - (float)x0;
            const float wy = py - (float)y0;
            const float wz = pz - (float)z0;

            const float w00 = (1.0f - wy) * (1.0f - wx);
            const float w01 = (1.0f - wy) * wx;
            const float w10 = wy * (1.0f - wx);
            const float w11 = wy * wx;
            const u64 w00p = pk2(w00, w00), w01p = pk2(w01, w01);
            const u64 w10p = pk2(w10, w10), w11p = pk2(w11, w11);
            const u64 lz0p = pk2(1.0f - wz, 1.0f - wz), wzp = pk2(wz, wz);

            const __half* gp = g_planes_h + (size_t)q * (RES * RES * PADC);
            const uint4 u00 = __ldg(reinterpret_cast<const uint4*>(gp + ((size_t)(y0 * RES) + x0) * PADC) + t);
            const uint4 u01 = __ldg(reinterpret_cast<const uint4*>(gp + ((size_t)(y0 * RES) + x1) * PADC) + t);
            const uint4 u10 = __ldg(reinterpret_cast<const uint4*>(gp + ((size_t)(y1 * RES) + x0) * PADC) + t);
            const uint4 u11 = __ldg(reinterpret_cast<const uint4*>(gp + ((size_t)(y1 * RES) + x1) * PADC) + t);
            const uint4 a0  = __ldg(reinterpret_cast<const uint4*>(g_lines_h + (q * RES + z0) * PADC) + t);
            const uint4 a1  = __ldg(reinterpret_cast<const uint4*>(g_lines_h + (q * RES + z1) * PADC) + t);

            #pragma unroll
            for (int k = 0; k < 4; k++) {
                const u64 f00 = h2f2((&u00.x)[k]);
                const u64 f01 = h2f2((&u01.x)[k]);
                const u64 f10 = h2f2((&u10.x)[k]);
                const u64 f11 = h2f2((&u11.x)[k]);
                const u64 g0  = h2f2((&a0.x)[k]);
                const u64 g1  = h2f2((&a1.x)[k]);

                const u64 pv = f2fma(f00, w00p,
                                f2fma(f01, w01p,
                                 f2fma(f10, w10p, f2mul(f11, w11p))));
                const u64 lv = f2fma(g0, lz0p, f2mul(g1, wzp));
                acc[k] = f2fma(pv, lv, acc[k]);
            }
        }

        // Stage vm (t=6,7 write zero pad in-bounds).
        {
            const float2 a0 = upk2(acc[0]), a1 = upk2(acc[1]);
            const float2 a2 = upk2(acc[2]), a3 = upk2(acc[3]);
            float4* dst = reinterpret_cast<float4*>(&s_vm[warp][sp][t * 4]);
            dst[0] = make_float4(a0.x, a0.y, a1.x, a1.y);
            dst[1] = make_float4(a2.x, a2.y, a3.x, a3.y);
        }
        __syncwarp();

        // Matvec, c4-outer; scatter by original index (one 128B line/point).
        {
            u64 s2[4];
            #pragma unroll
            for (int h = 0; h < 4; h++) s2[h] = pk2(0.0f, 0.0f);

            #pragma unroll
            for (int c4 = 0; c4 < 12; c4++) {
                const u64 w0 = s_w[2 * c4 + 0][o];
                const u64 w1 = s_w[2 * c4 + 1][o];
                #pragma unroll
                for (int h = 0; h < 4; h++) {
                    const uint4 v = reinterpret_cast<const uint4*>(s_vm[warp][h])[c4];
                    s2[h] = f2fma(mkpair(v.x, v.y), w0, s2[h]);
                    s2[h] = f2fma(mkpair(v.z, v.w), w1, s2[h]);
                }
            }

            #pragma unroll
            for (int h = 0; h < 4; h++) {
                const int idx = __float_as_int(__shfl_sync(0xffffffffu, cvv.w, h));
                if (pb + h < npts) {
                    const float2 f = upk2(s2[h]);
                    __stcs(out + (size_t)idx * OUT_C + o, f.x + f.y + bo);
                }
            }
        }
        __syncwarp();
        cvv = cvn;
    }
}

// ---------------------------------------------------------------------------
extern "C" void kernel_launch(void* const* d_in, const int* in_sizes, int n_in,
                              void* d_out, int out_size) {
    const float* coords = (const float*)d_in[0];
    const float* pxy    = (const float*)d_in[1];
    const float* pxz    = (const float*)d_in[2];
    const float* pyz    = (const float*)d_in[3];
    const float* lz     = (const float*)d_in[4];
    const float* ly     = (const float*)d_in[5];
    const float* lx     = (const float*)d_in[6];
    const float* pw     = (const float*)d_in[7];
    const float* pbias  = (const float*)d_in[8];
    float* outp = (float*)d_out;
    const int npts = in_sizes[0] / 3;

    dim3 tgrid(4, RES, 4);
    prep_grids<<<tgrid, 256>>>(pxy, pxz, pyz, lz, ly, lx);
    zero_hist<<<NBUCK / 256, 256>>>();
    hist_kernel<<<(npts + 255) / 256, 256>>>(coords, npts);
    scan_blocksum<<<128, 256>>>();
    scan_blockoff<<<1, 128>>>();
    scan_local<<<128, 256>>>();
    scatter_kernel<<<(npts + 255) / 256, 256>>>(coords, npts);
    geo_main<<<592, 256>>>(pw, pbias, outp, npts);
}

// round 11
// speedup vs baseline: 1.0509x; 1.0165x over previous
#include <cuda_runtime.h>
#include <cuda_fp16.h>
#include <cuda_bf16.h>
#include <cstdint>

// GeoEncoder v10: Morton sort overlapped with plane transpose via fork-join
// streams (independent work), scan fused to fewer launches.

#define RES   512
#define RANK  48
#define PADC  64
#define OUT_C 32
#define NBUCK 32768            // 15-bit Morton key (5 bits/axis)

typedef unsigned long long u64;

__device__ __half g_planes_h[3ull * RES * RES * PADC];  // ~100 MB
__device__ __half g_lines_h[3 * RES * PADC];            // 192 KB
__device__ unsigned g_hist[NBUCK];
__device__ unsigned g_cursor[NBUCK];
__device__ unsigned g_blocksum[128];
__device__ float4 g_sorted[1000192];                     // sorted coords + idx

// ---- packed f32x2 helpers -------------------------------------------------
__device__ __forceinline__ u64 pk2(float lo, float hi) {
    u64 r; asm("mov.b64 %0,{%1,%2};" : "=l"(r) : "f"(lo), "f"(hi)); return r;
}
__device__ __forceinline__ float2 upk2(u64 a) {
    float2 f; asm("mov.b64 {%0,%1},%2;" : "=f"(f.x), "=f"(f.y) : "l"(a)); return f;
}
__device__ __forceinline__ u64 f2fma(u64 a, u64 b, u64 c) {
    u64 d; asm("fma.rn.f32x2 %0,%1,%2,%3;" : "=l"(d) : "l"(a), "l"(b), "l"(c)); return d;
}
__device__ __forceinline__ u64 f2mul(u64 a, u64 b) {
    u64 d; asm("mul.rn.f32x2 %0,%1,%2;" : "=l"(d) : "l"(a), "l"(b)); return d;
}
__device__ __forceinline__ u64 h2f2(unsigned h) {
    float2 f = __half22float2(*reinterpret_cast<const __half2*>(&h));
    return pk2(f.x, f.y);
}
__device__ __forceinline__ u64 mkpair(unsigned lo, unsigned hi) {
    u64 r; asm("mov.b64 %0,{%1,%2};" : "=l"(r) : "r"(lo), "r"(hi)); return r;
}

// ---- Morton helpers -------------------------------------------------------
__device__ __forceinline__ unsigned spread3(unsigned x) {
    x &= 0x3ff;
    x = (x | (x << 16)) & 0x030000FF;
    x = (x | (x <<  8)) & 0x0300F00F;
    x = (x | (x <<  4)) & 0x030C30C3;
    x = (x | (x <<  2)) & 0x09249249;
    return x;
}
__device__ __forceinline__ unsigned morton_key(float x, float y, float z) {
    unsigned xq = min(31, (int)(fminf(fmaxf(x, 0.0f), 0.999999f) * 32.0f));
    unsigned yq = min(31, (int)(fminf(fmaxf(y, 0.0f), 0.999999f) * 32.0f));
    unsigned zq = min(31, (int)(fminf(fmaxf(z, 0.0f), 0.999999f) * 32.0f));
    return spread3(xq) | (spread3(yq) << 1) | (spread3(zq) << 2);
}

// ---------------------------------------------------------------------------
// Prep: planes -> [p][y][x][64] fp16; lines -> [l][z][64] fp16. z==3 = lines.
// ---------------------------------------------------------------------------
__global__ void prep_grids(const float* __restrict__ pxy,
                           const float* __restrict__ pxz,
                           const float* __restrict__ pyz,
                           const float* __restrict__ lz,
                           const float* __restrict__ ly,
                           const float* __restrict__ lx) {
    if (blockIdx.z == 3) {
        const int total = 3 * RES * PADC;
        int i = ((blockIdx.y * gridDim.x + blockIdx.x) * blockDim.x) + threadIdx.x;
        if (i < total) {
            int p   = i / (RES * PADC);
            int rem = i - p * (RES * PADC);
            int z   = rem / PADC;
            int r   = rem - z * PADC;
            const float* in = (p == 0) ? lz : (p == 1) ? ly : lx;
            g_lines_h[i] = (r < RANK) ? __float2half(in[r * RES + z]) : __half(0.0f);
        }
        return;
    }
    __shared__ float s[128 * 49];
    const int p  = blockIdx.z;
    const int y  = blockIdx.y;
    const int xb = blockIdx.x * 128;
    const float* in = (p == 0) ? pxy : (p == 1) ? pxz : pyz;

    for (int i = threadIdx.x; i < RANK * 128; i += blockDim.x) {
        int r  = i >> 7;
        int xl = i & 127;
        s[xl * 49 + r] = in[(size_t)r * (RES * RES) + (size_t)y * RES + xb + xl];
    }
    __syncthreads();

    __half2* outp = reinterpret_cast<__half2*>(
        g_planes_h + ((size_t)p * (RES * RES) + (size_t)y * RES + xb) * PADC);
    for (int i = threadIdx.x; i < 128 * (PADC / 2); i += blockDim.x) {
        int xl = i >> 5;
        int c  = (i & 31) * 2;
        float a = (c     < RANK) ? s[xl * 49 + c]     : 0.0f;
        float b = (c + 1 < RANK) ? s[xl * 49 + c + 1] : 0.0f;
        outp[i] = __floats2half2_rn(a, b);
    }
}

// ---------------------------------------------------------------------------
// Sort pipeline: zero -> hist -> blocksum -> local scan (w/ inlined block
// offsets) -> scatter.  Runs on a side stream, overlapped with prep_grids.
// ---------------------------------------------------------------------------
__global__ void zero_hist() {
    int i = blockIdx.x * blockDim.x + threadIdx.x;
    if (i < NBUCK) g_hist[i] = 0;
}

__global__ void hist_kernel(const float* __restrict__ coords, int npts) {
    int i = blockIdx.x * blockDim.x + threadIdx.x;
    if (i < npts) {
        float x = __ldcs(coords + 3 * i), y = __ldcs(coords + 3 * i + 1),
              z = __ldcs(coords + 3 * i + 2);
        atomicAdd(&g_hist[morton_key(x, y, z)], 1u);
    }
}

// Per-block (256-bin) totals. 128 blocks x 256 threads.
__global__ void scan_blocksum() {
    __shared__ unsigned red[256];
    const int tid = threadIdx.x;
    unsigned v = g_hist[blockIdx.x * 256 + tid];
    red[tid] = v;
    __syncthreads();
    for (int off = 128; off > 0; off >>= 1) {
        if (tid < off) red[tid] += red[tid + off];
        __syncthreads();
    }
    if (tid == 0) g_blocksum[blockIdx.x] = red[0];
}

// Local exclusive scan + inlined exclusive scan of the 128 block totals.
__global__ void scan_local_fused() {
    __shared__ unsigned s[256];
    __shared__ unsigned bs[128];
    const int tid  = threadIdx.x;
    const int base = blockIdx.x * 256;

    if (tid < 128) bs[tid] = g_blocksum[tid];
    unsigned v = g_hist[base + tid];
    s[tid] = v;
    __syncthreads();

    // Scan the 128 block sums (inclusive) with the first 128 threads.
    for (int off = 1; off < 128; off <<= 1) {
        unsigned u = (tid < 128 && tid >= off) ? bs[tid - off] : 0u;
        __syncthreads();
        if (tid < 128) bs[tid] += u;
        __syncthreads();
    }
    // Scan the 256 local bins (inclusive).
    for (int off = 1; off < 256; off <<= 1) {
        unsigned u = (tid >= off) ? s[tid - off] : 0u;
        __syncthreads();
        s[tid] += u;
        __syncthreads();
    }
    const unsigned boff = (blockIdx.x == 0) ? 0u : bs[blockIdx.x - 1];
    g_cursor[base + tid] = s[tid] - v + boff;
}

__global__ void scatter_kernel(const float* __restrict__ coords, int npts) {
    int i = blockIdx.x * blockDim.x + threadIdx.x;
    if (i < npts) {
        float x = __ldcs(coords + 3 * i), y = __ldcs(coords + 3 * i + 1),
              z = __ldcs(coords + 3 * i + 2);
        unsigned pos = atomicAdd(&g_cursor[morton_key(x, y, z)], 1u);
        __stcs(&g_sorted[pos], make_float4(x, y, z, __int_as_float(i)));
    }
}

// ---------------------------------------------------------------------------
// Main kernel. CTA owns a contiguous sorted block; 8 warps interleave 4-point
// groups so all warps share one L1 texel window. Coord prefetch.
// ---------------------------------------------------------------------------
__global__ void __launch_bounds__(256, 4)
geo_main(const float* __restrict__ projw,
         const float* __restrict__ projb,
         float* __restrict__ out, int npts) {
    __shared__ alignas(16) u64 s_vm[8][4][32];
    __shared__ u64 s_w[24][OUT_C];

    const int tid  = threadIdx.x;
    const int warp = tid >> 5;
    const int lane = tid & 31;
    const int sp   = lane >> 3;
    const int t    = lane & 7;
    const int o    = lane;

    for (int i = tid; i < 24 * OUT_C; i += blockDim.x) {
        int c2 = i >> 5, oo = i & 31;
        s_w[c2][oo] = pk2(projw[oo * RANK + 2 * c2], projw[oo * RANK + 2 * c2 + 1]);
    }
    __syncthreads();
    const float bo = projb[o];

    const int perCta = ((npts + gridDim.x * 32 - 1) / (gridDim.x * 32)) * 32;
    const int cbase  = blockIdx.x * perCta;
    const int cend   = min(npts, cbase + perCta);

    int pb = cbase + warp * 4;
    float4 cvv = make_float4(0.f, 0.f, 0.f, 0.f);
    if (pb < cend && lane < 4)
        cvv = __ldcs(&g_sorted[min(pb + lane, npts - 1)]);

    for (; pb < cend; pb += 32) {
        float4 cvn = make_float4(0.f, 0.f, 0.f, 0.f);
        const int pbn = pb + 32;
        if (pbn < cend && lane < 4)
            cvn = __ldcs(&g_sorted[min(pbn + lane, npts - 1)]);

        const float cx = __shfl_sync(0xffffffffu, cvv.x, sp) * 2.0f - 1.0f;
        const float cy = __shfl_sync(0xffffffffu, cvv.y, sp) * 2.0f - 1.0f;
        const float cz = __shfl_sync(0xffffffffu, cvv.z, sp) * 2.0f - 1.0f;

        u64 acc[4];
        #pragma unroll
        for (int k = 0; k < 4; k++) acc[k] = pk2(0.0f, 0.0f);

        #pragma unroll
        for (int q = 0; q < 3; q++) {
            const float gx = (q == 2) ? cy : cx;
            const float gy = (q == 0) ? cy : cz;
            const float gl = (q == 0) ? cz : ((q == 1) ? cy : cx);

            float px = fminf(fmaxf((gx + 1.0f) * 0.5f * 511.0f, 0.0f), 511.0f);
            float py = fminf(fmaxf((gy + 1.0f) * 0.5f * 511.0f, 0.0f), 511.0f);
            float pz = fminf(fmaxf((gl + 1.0f) * 0.5f * 511.0f, 0.0f), 511.0f);
            const int x0 = (int)floorf(px), y0 = (int)floorf(py), z0 = (int)floorf(pz);
            const int x1 = min(x0 + 1, 511), y1 = min(y0 + 1, 511), z1 = min(z0 + 1, 511);
            const float wx = px - (float)x0;
            const float wy = py - (float)y0;
            const float wz = pz - (float)z0;

            const float w00 = (1.0f - wy) * (1.0f - wx);
            const float w01 = (1.0f - wy) * wx;
            const float w10 = wy * (1.0f - wx);
            const float w11 = wy * wx;
            const u64 w00p = pk2(w00, w00), w01p = pk2(w01, w01);
            const u64 w10p = pk2(w10, w10), w11p = pk2(w11, w11);
            const u64 lz0p = pk2(1.0f - wz, 1.0f - wz), wzp = pk2(wz, wz);

            const __half* gp = g_planes_h + (size_t)q * (RES * RES * PADC);
            const uint4 u00 = __ldg(reinterpret_cast<const uint4*>(gp + ((size_t)(y0 * RES) + x0) * PADC) + t);
            const uint4 u01 = __ldg(reinterpret_cast<const uint4*>(gp + ((size_t)(y0 * RES) + x1) * PADC) + t);
            const uint4 u10 = __ldg(reinterpret_cast<const uint4*>(gp + ((size_t)(y1 * RES) + x0) * PADC) + t);
            const uint4 u11 = __ldg(reinterpret_cast<const uint4*>(gp + ((size_t)(y1 * RES) + x1) * PADC) + t);
            const uint4 a0  = __ldg(reinterpret_cast<const uint4*>(g_lines_h + (q * RES + z0) * PADC) + t);
            const uint4 a1  = __ldg(reinterpret_cast<const uint4*>(g_lines_h + (q * RES + z1) * PADC) + t);

            #pragma unroll
            for (int k = 0; k < 4; k++) {
                const u64 f00 = h2f2((&u00.x)[k]);
                const u64 f01 = h2f2((&u01.x)[k]);
                const u64 f10 = h2f2((&u10.x)[k]);
                const u64 f11 = h2f2((&u11.x)[k]);
                const u64 g0  = h2f2((&a0.x)[k]);
                const u64 g1  = h2f2((&a1.x)[k]);

                const u64 pv = f2fma(f00, w00p,
                                f2fma(f01, w01p,
                                 f2fma(f10, w10p, f2mul(f11, w11p))));
                const u64 lv = f2fma(g0, lz0p, f2mul(g1, wzp));
                acc[k] = f2fma(pv, lv, acc[k]);
            }
        }

        {
            const float2 a0 = upk2(acc[0]), a1 = upk2(acc[1]);
            const float2 a2 = upk2(acc[2]), a3 = upk2(acc[3]);
            float4* dst = reinterpret_cast<float4*>(&s_vm[warp][sp][t * 4]);
            dst[0] = make_float4(a0.x, a0.y, a1.x, a1.y);
            dst[1] = make_float4(a2.x, a2.y, a3.x, a3.y);
        }
        __syncwarp();

        {
            u64 s2[4];
            #pragma unroll
            for (int h = 0; h < 4; h++) s2[h] = pk2(0.0f, 0.0f);

            #pragma unroll
            for (int c4 = 0; c4 < 12; c4++) {
                const u64 w0 = s_w[2 * c4 + 0][o];
                const u64 w1 = s_w[2 * c4 + 1][o];
                #pragma unroll
                for (int h = 0; h < 4; h++) {
                    const uint4 v = reinterpret_cast<const uint4*>(s_vm[warp][h])[c4];
                    s2[h] = f2fma(mkpair(v.x, v.y), w0, s2[h]);
                    s2[h] = f2fma(mkpair(v.z, v.w), w1, s2[h]);
                }
            }

            #pragma unroll
            for (int h = 0; h < 4; h++) {
                const int idx = __float_as_int(__shfl_sync(0xffffffffu, cvv.w, h));
                if (pb + h < npts) {
                    const float2 f = upk2(s2[h]);
                    __stcs(out + (size_t)idx * OUT_C + o, f.x + f.y + bo);
                }
            }
        }
        __syncwarp();
        cvv = cvn;
    }
}

// ---------------------------------------------------------------------------
extern "C" void kernel_launch(void* const* d_in, const int* in_sizes, int n_in,
                              void* d_out, int out_size) {
    const float* coords = (const float*)d_in[0];
    const float* pxy    = (const float*)d_in[1];
    const float* pxz    = (const float*)d_in[2];
    const float* pyz    = (const float*)d_in[3];
    const float* lz     = (const float*)d_in[4];
    const float* ly     = (const float*)d_in[5];
    const float* lx     = (const float*)d_in[6];
    const float* pw     = (const float*)d_in[7];
    const float* pbias  = (const float*)d_in[8];
    float* outp = (float*)d_out;
    const int npts = in_sizes[0] / 3;

    // One-time host-side stream/event setup (created during the uncaptured
    // correctness call; the captured graph and per-call device work are
    // identical on every call). No device memory is allocated.
    static cudaStream_t s_side = nullptr;
    static cudaEvent_t  s_evRoot = nullptr, s_evSide = nullptr;
    static bool s_tried = false;
    if (!s_tried) {
        s_tried = true;
        if (cudaStreamCreateWithFlags(&s_side, cudaStreamNonBlocking) != cudaSuccess)
            s_side = nullptr;
        if (s_side) {
            if (cudaEventCreateWithFlags(&s_evRoot, cudaEventDisableTiming) != cudaSuccess ||
                cudaEventCreateWithFlags(&s_evSide, cudaEventDisableTiming) != cudaSuccess)
                s_side = nullptr;
        }
    }

    dim3 tgrid(4, RES, 4);

    if (s_side) {
        // Fork: sort chain on side stream, prep on main; join before geo_main.
        cudaEventRecord(s_evRoot, 0);
        cudaStreamWaitEvent(s_side, s_evRoot, 0);

        zero_hist<<<NBUCK / 256, 256, 0, s_side>>>();
        hist_kernel<<<(npts + 255) / 256, 256, 0, s_side>>>(coords, npts);
        scan_blocksum<<<128, 256, 0, s_side>>>();
        scan_local_fused<<<128, 256, 0, s_side>>>();
        scatter_kernel<<<(npts + 255) / 256, 256, 0, s_side>>>(coords, npts);
        cudaEventRecord(s_evSide, s_side);

        prep_grids<<<tgrid, 256>>>(pxy, pxz, pyz, lz, ly, lx);
        cudaStreamWaitEvent(0, s_evSide, 0);
        geo_main<<<592, 256>>>(pw, pbias, outp, npts);
    } else {
        // Sequential fallback.
        prep_grids<<<tgrid, 256>>>(pxy, pxz, pyz, lz, ly, lx);
        zero_hist<<<NBUCK / 256, 256>>>();
        hist_kernel<<<(npts + 255) / 256, 256>>>(coords, npts);
        scan_blocksum<<<128, 256>>>();
        scan_local_fused<<<128, 256>>>();
        scatter_kernel<<<(npts + 255) / 256, 256>>>(coords, npts);
        geo_main<<<592, 256>>>(pw, pbias, outp, npts);
    }
}